// round 1
// baseline (speedup 1.0000x reference)
#include <cuda_runtime.h>
#include <math.h>

// Problem constants
#define Bb   1024
#define Uu   8
#define Ss   50
#define Ll   200
#define Ff   4
#define Ee   32
#define Dd   128      // F*E
#define UE   256      // U*E
#define G4   512      // 4*D
#define NEGV -1000000000.0f

// ---------------- scratch (static device globals; no runtime alloc) ----------
__device__ float  g_user_e[Bb * UE];          // (B,256)
__device__ float  g_stx   [Bb * Ss * Dd];     // (B,50,128) embedded short-term
__device__ float  g_xW    [Bb * Ss * G4];     // (B,50,512) x@W+b precompute
__device__ float  g_hs    [Bb * Ss * Dd];     // LSTM outputs
__device__ float  g_q     [Bb * Ss * Dd];
__device__ float  g_k     [Bb * Ss * Dd];
__device__ float  g_v     [Bb * Ss * Dd];
__device__ float  g_att   [Bb * Ss * Dd];     // attention out (pre-Wo)
__device__ float  g_stm   [Bb * Ss * Dd];     // MHA out (post-Wo)
__device__ float  g_qvec  [Bb * Dd];
__device__ float  g_short [Bb * Dd];
__device__ float  g_long  [Bb * Dd];
__device__ float4 g_Ur    [Dd * Dd];          // repacked lstm_U: [k][d] = (i,f,g,o)

__device__ __forceinline__ float sigm(float x) { return 1.0f / (1.0f + __expf(-x)); }

// ---------------- 1) embedding gathers --------------------------------------
__global__ void gather_kernel(const int* __restrict__ up, const int* __restrict__ stb,
                              const float* __restrict__ emb) {
    int idx = blockIdx.x * blockDim.x + threadIdx.x;
    const int n1 = Bb * UE;
    if (idx < n1) {
        int b = idx / UE, r = idx % UE;
        int u = r / Ee, e = r % Ee;
        g_user_e[idx] = emb[up[b * Uu + u] * Ee + e];
    }
    int idx2 = idx - n1;
    if (idx2 >= 0 && idx2 < Bb * Ss * Dd) {
        int e = idx2 & (Ee - 1);
        int t = idx2 / Ee;            // (b*S+s)*F + f
        int f = t & (Ff - 1);
        int bs = t / Ff;              // b*S+s
        g_stx[idx2] = emb[stb[bs * Ff + f] * Ee + e];
    }
}

// ---------------- 2) repack lstm_U into gate-major float4 -------------------
__global__ void repackU_kernel(const float* __restrict__ Uw) {
    int idx = blockIdx.x * blockDim.x + threadIdx.x;   // 16384
    if (idx >= Dd * Dd) return;
    int k = idx >> 7, d = idx & 127;
    const float* r = Uw + k * G4;
    g_Ur[idx] = make_float4(r[d], r[d + 128], r[d + 256], r[d + 384]);
}

// ---------------- generic fp32 GEMM: C[M,N] = A[M,K] @ W[K,N] (+bias) -------
// BM=BN=64, BK=16, 256 threads, 4x4 microtile. M%64==0, N%64==0, K%16==0.
__global__ __launch_bounds__(256) void gemm64_kernel(
    const float* __restrict__ A, const float* __restrict__ W,
    const float* __restrict__ bias, float* __restrict__ C,
    int M, int N, int K) {
    __shared__ __align__(16) float As[16][68];  // [k][m], padded
    __shared__ __align__(16) float Ws[16][68];  // [k][n], padded
    int tid = threadIdx.x;
    int tx = tid & 15, ty = tid >> 4;
    int m0 = blockIdx.y * 64, n0 = blockIdx.x * 64;
    int ar = tid >> 2, ac4 = (tid & 3) * 4;     // A tile: row ar, k-offset ac4
    int wr = tid >> 4, wc4 = (tid & 15) * 4;    // W tile: k wr, n-offset wc4
    float acc[4][4] = {};
    for (int k0 = 0; k0 < K; k0 += 16) {
        float4 a4 = *(const float4*)&A[(m0 + ar) * K + k0 + ac4];
        float4 w4 = *(const float4*)&W[(k0 + wr) * N + n0 + wc4];
        __syncthreads();
        As[ac4 + 0][ar] = a4.x; As[ac4 + 1][ar] = a4.y;
        As[ac4 + 2][ar] = a4.z; As[ac4 + 3][ar] = a4.w;
        *(float4*)&Ws[wr][wc4] = w4;
        __syncthreads();
#pragma unroll
        for (int kk = 0; kk < 16; kk++) {
            float4 av = *(const float4*)&As[kk][ty * 4];
            float4 wv = *(const float4*)&Ws[kk][tx * 4];
            acc[0][0] += av.x * wv.x; acc[0][1] += av.x * wv.y; acc[0][2] += av.x * wv.z; acc[0][3] += av.x * wv.w;
            acc[1][0] += av.y * wv.x; acc[1][1] += av.y * wv.y; acc[1][2] += av.y * wv.z; acc[1][3] += av.y * wv.w;
            acc[2][0] += av.z * wv.x; acc[2][1] += av.z * wv.y; acc[2][2] += av.z * wv.z; acc[2][3] += av.z * wv.w;
            acc[3][0] += av.w * wv.x; acc[3][1] += av.w * wv.y; acc[3][2] += av.w * wv.z; acc[3][3] += av.w * wv.w;
        }
    }
    float b0x = 0.f, b0y = 0.f, b0z = 0.f, b0w = 0.f;
    if (bias) {
        const float* bp = bias + n0 + tx * 4;
        b0x = bp[0]; b0y = bp[1]; b0z = bp[2]; b0w = bp[3];
    }
#pragma unroll
    for (int i = 0; i < 4; i++) {
        float4 o = make_float4(acc[i][0] + b0x, acc[i][1] + b0y,
                               acc[i][2] + b0z, acc[i][3] + b0w);
        *(float4*)&C[(m0 + ty * 4 + i) * N + n0 + tx * 4] = o;
    }
}

// ---------------- 3) LSTM recurrence: persistent, batch-parallel ------------
// 128 blocks x 8 batch rows; 512 threads: thread = (bg<2 rows>, d). Inner
// loop: 1 LDG.128 (gate-packed U) + 2 broadcast LDS (h) + 8 FFMA.
__global__ __launch_bounds__(512) void lstm_kernel(const float* __restrict__ xW,
                                                   float* __restrict__ hs) {
    __shared__ float h_s[8][128];
    int t = threadIdx.x;
    int d = t & 127, bg = t >> 7;          // bg in 0..3
    int r0 = bg * 2, r1 = r0 + 1;
    int b0 = blockIdx.x * 8;
    for (int i = t; i < 8 * 128; i += 512) ((float*)h_s)[i] = 0.0f;
    float cc0 = 0.0f, cc1 = 0.0f;
    __syncthreads();
    for (int step = 0; step < Ss; step++) {
        int base0 = ((b0 + r0) * Ss + step) * G4;
        int base1 = ((b0 + r1) * Ss + step) * G4;
        float4 a0 = make_float4(xW[base0 + d], xW[base0 + d + 128],
                                xW[base0 + d + 256], xW[base0 + d + 384]);
        float4 a1 = make_float4(xW[base1 + d], xW[base1 + d + 128],
                                xW[base1 + d + 256], xW[base1 + d + 384]);
#pragma unroll 4
        for (int k = 0; k < 128; k++) {
            float4 u = g_Ur[k * 128 + d];
            float h0 = h_s[r0][k], h1 = h_s[r1][k];
            a0.x += u.x * h0; a0.y += u.y * h0; a0.z += u.z * h0; a0.w += u.w * h0;
            a1.x += u.x * h1; a1.y += u.y * h1; a1.z += u.z * h1; a1.w += u.w * h1;
        }
        float i0 = sigm(a0.x), f0 = sigm(a0.y), gg0 = tanhf(a0.z), o0 = sigm(a0.w);
        float i1 = sigm(a1.x), f1 = sigm(a1.y), gg1 = tanhf(a1.z), o1 = sigm(a1.w);
        cc0 = f0 * cc0 + i0 * gg0;  float hh0 = o0 * tanhf(cc0);
        cc1 = f1 * cc1 + i1 * gg1;  float hh1 = o1 * tanhf(cc1);
        __syncthreads();
        h_s[r0][d] = hh0; h_s[r1][d] = hh1;
        hs[((b0 + r0) * Ss + step) * Dd + d] = hh0;
        hs[((b0 + r1) * Ss + step) * Dd + d] = hh1;
        __syncthreads();
    }
}

// ---------------- 4) MHA core: one block per (b, head) ----------------------
__global__ __launch_bounds__(128) void mha_kernel() {
    int bh = blockIdx.x;
    int b = bh >> 2, h = bh & 3;
    __shared__ float qs[Ss][Ee], ks[Ss][Ee], vs[Ss][Ee];
    __shared__ float sc[Ss][52];
    int t = threadIdx.x;
    for (int idx = t; idx < Ss * Ee; idx += 128) {
        int s = idx >> 5, e = idx & 31;
        int g = (b * Ss + s) * Dd + h * Ee + e;
        qs[s][e] = g_q[g]; ks[s][e] = g_k[g]; vs[s][e] = g_v[g];
    }
    __syncthreads();
    const float scale = 0.17677669529663687f;  // 1/sqrt(32)
    for (int idx = t; idx < Ss * Ss; idx += 128) {
        int r = idx / Ss, c = idx % Ss;
        float a = 0.f;
#pragma unroll
        for (int e = 0; e < Ee; e++) a += qs[r][e] * ks[c][e];
        sc[r][c] = a * scale;
    }
    __syncthreads();
    if (t < Ss) {
        float mx = -3.4e38f;
        for (int c = 0; c < Ss; c++) mx = fmaxf(mx, sc[t][c]);
        float sm = 0.f;
        for (int c = 0; c < Ss; c++) { float e = __expf(sc[t][c] - mx); sc[t][c] = e; sm += e; }
        float inv = 1.f / sm;
        for (int c = 0; c < Ss; c++) sc[t][c] *= inv;
    }
    __syncthreads();
    for (int idx = t; idx < Ss * Ee; idx += 128) {
        int s = idx >> 5, e = idx & 31;
        float a = 0.f;
        for (int c = 0; c < Ss; c++) a += sc[s][c] * vs[c][e];
        g_att[(b * Ss + s) * Dd + h * Ee + e] = a;
    }
}

// ---------------- 5) short-term attention pooling ---------------------------
__global__ __launch_bounds__(128) void shortpool_kernel() {
    int b = blockIdx.x;
    __shared__ float qv[Dd];
    __shared__ float sc[Ss];
    int t = threadIdx.x;
    qv[t] = g_qvec[b * Dd + t];
    __syncthreads();
    if (t < Ss) {
        const float* row = &g_stm[(b * Ss + t) * Dd];
        float a = 0.f;
        for (int k = 0; k < Dd; k++) a += row[k] * qv[k];
        sc[t] = a;
    }
    __syncthreads();
    if (t == 0) {
        float mx = -3.4e38f;
        for (int s = 0; s < Ss; s++) mx = fmaxf(mx, sc[s]);
        float sm = 0.f;
        for (int s = 0; s < Ss; s++) { float e = __expf(sc[s] - mx); sc[s] = e; sm += e; }
        float inv = 1.f / sm;
        for (int s = 0; s < Ss; s++) sc[s] *= inv;
    }
    __syncthreads();
    float a = 0.f;
    for (int s = 0; s < Ss; s++) a += sc[s] * g_stm[(b * Ss + s) * Dd + t];
    g_short[b * Dd + t] = a;
}

// ---------------- 6) long-term field attention (dedup mask) -----------------
__global__ __launch_bounds__(256) void longterm_kernel(const int* __restrict__ ltb,
                                                       const float* __restrict__ emb,
                                                       const float* __restrict__ Wt,
                                                       const float* __restrict__ bt) {
    int bi = blockIdx.x;
    int b = bi >> 2, fi = bi & 3;
    __shared__ int   ids[Ll];
    __shared__ float vecs[Ll][Ee];
    __shared__ float sc[Ll];
    __shared__ float uv[Ee];
    __shared__ float part[8][Ee];
    __shared__ float red[256];
    int t = threadIdx.x;
    if (t < Ll) ids[t] = ltb[(b * Ll + t) * Ff + fi];
    __syncthreads();
    for (int idx = t; idx < Ll * Ee; idx += 256) {
        int l = idx >> 5, e = idx & 31;
        vecs[l][e] = emb[ids[l] * Ee + e];
    }
    {   // uv = user_e[b] @ Wt[fi] + bt[fi], split across 8 k-groups
        int e = t & 31, g = t >> 5;
        float a = 0.f;
        for (int k = g * 32; k < g * 32 + 32; k++)
            a += g_user_e[b * UE + k] * Wt[(fi * UE + k) * Ee + e];
        part[g][e] = a;
    }
    __syncthreads();
    if (t < Ee) {
        float a = bt[fi * Ee + t];
        for (int g = 0; g < 8; g++) a += part[g][t];
        uv[t] = a;
    }
    __syncthreads();
    if (t < Ll) {
        int mid = ids[t];
        bool keep = true;
        for (int j = 0; j < t; j++) if (ids[j] == mid) { keep = false; break; }
        float a = 0.f;
#pragma unroll
        for (int e = 0; e < Ee; e++) a += vecs[t][e] * uv[e];
        sc[t] = keep ? a : NEGV;
    }
    __syncthreads();
    // masked softmax over 200 (block reduce max then sum)
    red[t] = (t < Ll) ? sc[t] : -3.4e38f;
    __syncthreads();
    for (int ofs = 128; ofs >= 1; ofs >>= 1) {
        if (t < ofs) red[t] = fmaxf(red[t], red[t + ofs]);
        __syncthreads();
    }
    float mx = red[0];
    __syncthreads();
    float ev = (t < Ll) ? __expf(sc[t] - mx) : 0.f;
    if (t < Ll) sc[t] = ev;
    red[t] = ev;
    __syncthreads();
    for (int ofs = 128; ofs >= 1; ofs >>= 1) {
        if (t < ofs) red[t] += red[t + ofs];
        __syncthreads();
    }
    float inv = 1.f / red[0];
    __syncthreads();
    {   // weighted sum: 32 e x 8 l-groups
        int e = t & 31, g = t >> 5;
        float a = 0.f;
        for (int l = g; l < Ll; l += 8) a += sc[l] * vecs[l][e];
        part[g][e] = a;
    }
    __syncthreads();
    if (t < Ee) {
        float a = 0.f;
        for (int g = 0; g < 8; g++) a += part[g][t];
        g_long[b * Dd + fi * Ee + t] = a * inv;
    }
}

// ---------------- 7) final gate + mix ---------------------------------------
__global__ __launch_bounds__(128) void gate_kernel(
    const float* __restrict__ Wu, const float* __restrict__ bu,
    const float* __restrict__ Wsg, const float* __restrict__ bsg,
    const float* __restrict__ Wl, const float* __restrict__ bl,
    float* __restrict__ out) {
    int b = blockIdx.x, d = threadIdx.x;
    __shared__ float ue[UE], sh[Dd], lg[Dd];
    ue[d] = g_user_e[b * UE + d];
    ue[d + 128] = g_user_e[b * UE + 128 + d];
    sh[d] = g_short[b * Dd + d];
    lg[d] = g_long[b * Dd + d];
    __syncthreads();
    float a = bu[d] + bsg[d] + bl[d];
    for (int k = 0; k < UE; k++) a += ue[k] * Wu[k * Dd + d];
    for (int k = 0; k < Dd; k++) a += sh[k] * Wsg[k * Dd + d] + lg[k] * Wl[k * Dd + d];
    float g = sigm(a);
    out[b * Dd + d] = (1.f - g) * lg[d] + g * sh[d];
}

// ---------------- host ------------------------------------------------------
static float* sym(const void* s) {
    void* p = nullptr;
    cudaGetSymbolAddress(&p, s);
    return (float*)p;
}

extern "C" void kernel_launch(void* const* d_in, const int* in_sizes, int n_in,
                              void* d_out, int out_size) {
    const int*   up     = (const int*)d_in[0];
    const int*   stb    = (const int*)d_in[1];
    const int*   ltb    = (const int*)d_in[2];
    const float* emb    = (const float*)d_in[3];
    const float* lstm_W = (const float*)d_in[4];
    const float* lstm_U = (const float*)d_in[5];
    const float* lstm_b = (const float*)d_in[6];
    const float* Wq     = (const float*)d_in[7];
    const float* Wk     = (const float*)d_in[8];
    const float* Wv     = (const float*)d_in[9];
    const float* Wo     = (const float*)d_in[10];
    const float* W1     = (const float*)d_in[11];
    const float* b1     = (const float*)d_in[12];
    const float* Wt     = (const float*)d_in[13];
    const float* bt     = (const float*)d_in[14];
    const float* Wu     = (const float*)d_in[15];
    const float* bu     = (const float*)d_in[16];
    const float* Wsg    = (const float*)d_in[17];
    const float* bsg    = (const float*)d_in[18];
    const float* Wl     = (const float*)d_in[19];
    const float* bl     = (const float*)d_in[20];
    float* out = (float*)d_out;

    float* p_user  = sym(g_user_e);
    float* p_stx   = sym(g_stx);
    float* p_xW    = sym(g_xW);
    float* p_hs    = sym(g_hs);
    float* p_q     = sym(g_q);
    float* p_k     = sym(g_k);
    float* p_v     = sym(g_v);
    float* p_att   = sym(g_att);
    float* p_stm   = sym(g_stm);
    float* p_qvec  = sym(g_qvec);

    const int MBS = Bb * Ss;  // 51200

    // 1) gathers + U repack
    {
        int total = Bb * UE + Bb * Ss * Dd;
        gather_kernel<<<(total + 255) / 256, 256>>>(up, stb, emb);
        repackU_kernel<<<(Dd * Dd + 255) / 256, 256>>>(lstm_U);
    }
    // 2) xW = stx @ lstm_W + b   (51200 x 128 x 512)
    gemm64_kernel<<<dim3(G4 / 64, MBS / 64), 256>>>(p_stx, lstm_W, lstm_b, p_xW, MBS, G4, Dd);
    // 3) LSTM recurrence
    lstm_kernel<<<Bb / 8, 512>>>(p_xW, p_hs);
    // 4) Q/K/V projections (51200 x 128 x 128)
    gemm64_kernel<<<dim3(Dd / 64, MBS / 64), 256>>>(p_hs, Wq, nullptr, p_q, MBS, Dd, Dd);
    gemm64_kernel<<<dim3(Dd / 64, MBS / 64), 256>>>(p_hs, Wk, nullptr, p_k, MBS, Dd, Dd);
    gemm64_kernel<<<dim3(Dd / 64, MBS / 64), 256>>>(p_hs, Wv, nullptr, p_v, MBS, Dd, Dd);
    // 5) attention core + output projection
    mha_kernel<<<Bb * Ff, 128>>>();
    gemm64_kernel<<<dim3(Dd / 64, MBS / 64), 256>>>(p_att, Wo, nullptr, p_stm, MBS, Dd, Dd);
    // 6) pooling query + short-term pooling
    gemm64_kernel<<<dim3(Dd / 64, Bb / 64), 256>>>(p_user, W1, b1, p_qvec, Bb, Dd, UE);
    shortpool_kernel<<<Bb, 128>>>();
    // 7) long-term field attention
    longterm_kernel<<<Bb * Ff, 256>>>(ltb, emb, Wt, bt);
    // 8) gate + mix -> out
    gate_kernel<<<Bb, 128>>>(Wu, bu, Wsg, bsg, Wl, bl, out);
}

// round 2
// speedup vs baseline: 1.4570x; 1.4570x over previous
#include <cuda_runtime.h>
#include <math.h>
#include <stdint.h>

// Problem constants
#define Bb   1024
#define Uu   8
#define Ss   50
#define Ll   200
#define Ff   4
#define Ee   32
#define Dd   128      // F*E
#define UE   256      // U*E
#define G4   512      // 4*D
#define NEGV -1000000000.0f

// ---------------- scratch (static device globals) ---------------------------
__device__ float  g_user_e[Bb * UE];          // (B,256)
__device__ float  g_stx   [Bb * Ss * Dd];     // (B,50,128) tf32-rounded
__device__ float  g_xW    [Bb * Ss * G4];     // (B,50,512) x@W+b (fp32)
__device__ float  g_hs    [Bb * Ss * Dd];     // LSTM outputs (tf32-rounded)
__device__ float  g_qkv   [Bb * Ss * 384];    // fused q|k|v
__device__ float  g_att   [Bb * Ss * Dd];     // attn out, pre-Wo (tf32-rounded)
__device__ float  g_stm   [Bb * Ss * Dd];     // MHA out (post-Wo)
__device__ float  g_qvec  [Bb * Dd];
__device__ float  g_short [Bb * Dd];
__device__ float  g_long  [Bb * Dd];
__device__ float4 g_Ur    [Dd * Dd];          // repacked lstm_U (fp32, gate-packed)
__device__ float  g_Wr    [Dd * G4];          // tf32-rounded lstm_W
__device__ float  g_Wqkv  [Dd * 384];         // tf32-rounded packed Wq|Wk|Wv
__device__ float  g_Wor   [Dd * Dd];          // tf32-rounded Wo

__device__ __forceinline__ float sigm(float x) { return 1.0f / (1.0f + __expf(-x)); }

__device__ __forceinline__ float to_tf32(float x) {
    uint32_t u;
    asm("cvt.rna.tf32.f32 %0, %1;" : "=r"(u) : "f"(x));
    return __uint_as_float(u);
}

__device__ __forceinline__ void cp16(void* smem, const void* g) {
    uint32_t s = (uint32_t)__cvta_generic_to_shared(smem);
    asm volatile("cp.async.ca.shared.global [%0], [%1], 16;" :: "r"(s), "l"(g));
}

__device__ __forceinline__ void mma_tf32(float* c, const uint32_t* a, const uint32_t* b) {
    asm volatile(
        "mma.sync.aligned.m16n8k8.row.col.f32.tf32.tf32.f32 "
        "{%0,%1,%2,%3}, {%4,%5,%6,%7}, {%8,%9}, {%0,%1,%2,%3};"
        : "+f"(c[0]), "+f"(c[1]), "+f"(c[2]), "+f"(c[3])
        : "r"(a[0]), "r"(a[1]), "r"(a[2]), "r"(a[3]), "r"(b[0]), "r"(b[1]));
}

// ---------------- 1) embedding gathers (stx tf32-rounded) -------------------
__global__ void gather_kernel(const int* __restrict__ up, const int* __restrict__ stb,
                              const float* __restrict__ emb) {
    int idx = blockIdx.x * blockDim.x + threadIdx.x;
    const int n1 = Bb * UE;
    if (idx < n1) {
        int b = idx / UE, r = idx % UE;
        int u = r / Ee, e = r % Ee;
        g_user_e[idx] = emb[up[b * Uu + u] * Ee + e];
    }
    int idx2 = idx - n1;
    if (idx2 >= 0 && idx2 < Bb * Ss * Dd) {
        int e = idx2 & (Ee - 1);
        int t = idx2 / Ee;            // (b*S+s)*F + f
        int f = t & (Ff - 1);
        int bs = t / Ff;              // b*S+s
        g_stx[idx2] = to_tf32(emb[stb[bs * Ff + f] * Ee + e]);
    }
}

// ---------------- 2) weight repacks ----------------------------------------
__global__ void repackU_kernel(const float* __restrict__ Uw) {
    int idx = blockIdx.x * blockDim.x + threadIdx.x;   // 16384
    if (idx >= Dd * Dd) return;
    int k = idx >> 7, d = idx & 127;
    const float* r = Uw + k * G4;
    g_Ur[idx] = make_float4(r[d], r[d + 128], r[d + 256], r[d + 384]);
}

__global__ void repackW_kernel(const float* __restrict__ lstm_W,
                               const float* __restrict__ Wq,
                               const float* __restrict__ Wk,
                               const float* __restrict__ Wv,
                               const float* __restrict__ Wo) {
    int idx = blockIdx.x * blockDim.x + threadIdx.x;   // 131072 total
    if (idx < Dd * G4) {
        g_Wr[idx] = to_tf32(lstm_W[idx]);
        return;
    }
    int j = idx - Dd * G4;
    if (j < Dd * 384) {
        int k = j / 384, n = j % 384;
        float v = (n < 128) ? Wq[k * Dd + n]
                : (n < 256) ? Wk[k * Dd + (n - 128)]
                            : Wv[k * Dd + (n - 256)];
        g_Wqkv[j] = to_tf32(v);
        return;
    }
    j -= Dd * 384;
    if (j < Dd * Dd) g_Wor[j] = to_tf32(Wo[j]);
}

// ---------------- tf32 tensor-core GEMM: C[M,N]=A[M,K]@W[K,N] (+bias) -------
// BM=128, BN=128, BK=32, 256 threads (8 warps = 4m x 2n, warp tile 32x64).
// Requires M%128==0, N%128==0, K%32==0. A and W pre-rounded to tf32.
__global__ __launch_bounds__(256, 2) void gemm_tf32(
    const float* __restrict__ A, const float* __restrict__ W,
    const float* __restrict__ bias, float* __restrict__ C,
    int M, int N, int K) {
    __shared__ float As[128][36];   // [m][k], pad 4 -> frag loads conflict-free
    __shared__ float Bs[32][136];   // [k][n], pad 8 -> frag loads conflict-free
    int tid = threadIdx.x;
    int lane = tid & 31, warp = tid >> 5;
    int wm = warp >> 1, wn = warp & 1;
    int g = lane >> 2, tig = lane & 3;
    int m0 = blockIdx.y * 128, n0 = blockIdx.x * 128;

    float c[2][8][4];
#pragma unroll
    for (int i = 0; i < 2; i++)
#pragma unroll
        for (int j = 0; j < 8; j++)
#pragma unroll
            for (int l = 0; l < 4; l++) c[i][j][l] = 0.f;

    for (int k0 = 0; k0 < K; k0 += 32) {
        if (k0) __syncthreads();
#pragma unroll
        for (int i = 0; i < 4; i++) {      // A: 1024 float4
            int idx = tid + i * 256;
            int r = idx >> 3, c4 = (idx & 7) * 4;
            cp16(&As[r][c4], &A[(m0 + r) * K + k0 + c4]);
        }
#pragma unroll
        for (int i = 0; i < 4; i++) {      // B: 1024 float4
            int idx = tid + i * 256;
            int r = idx >> 5, c4 = (idx & 31) * 4;
            cp16(&Bs[r][c4], &W[(k0 + r) * N + n0 + c4]);
        }
        asm volatile("cp.async.commit_group;");
        asm volatile("cp.async.wait_group 0;");
        __syncthreads();

#pragma unroll
        for (int kk = 0; kk < 32; kk += 8) {
            uint32_t a[2][4], b[8][2];
#pragma unroll
            for (int mt = 0; mt < 2; mt++) {
                int mr = wm * 32 + mt * 16;
                a[mt][0] = __float_as_uint(As[mr + g][kk + tig]);
                a[mt][1] = __float_as_uint(As[mr + g + 8][kk + tig]);
                a[mt][2] = __float_as_uint(As[mr + g][kk + tig + 4]);
                a[mt][3] = __float_as_uint(As[mr + g + 8][kk + tig + 4]);
            }
#pragma unroll
            for (int nt = 0; nt < 8; nt++) {
                int nc = wn * 64 + nt * 8 + g;
                b[nt][0] = __float_as_uint(Bs[kk + tig][nc]);
                b[nt][1] = __float_as_uint(Bs[kk + tig + 4][nc]);
            }
#pragma unroll
            for (int mt = 0; mt < 2; mt++)
#pragma unroll
                for (int nt = 0; nt < 8; nt++)
                    mma_tf32(c[mt][nt], a[mt], b[nt]);
        }
    }

#pragma unroll
    for (int mt = 0; mt < 2; mt++) {
        int row = m0 + wm * 32 + mt * 16 + g;
#pragma unroll
        for (int nt = 0; nt < 8; nt++) {
            int col = n0 + wn * 64 + nt * 8 + 2 * tig;
            float bx = 0.f, by = 0.f;
            if (bias) { bx = bias[col]; by = bias[col + 1]; }
            float2 o0 = make_float2(c[mt][nt][0] + bx, c[mt][nt][1] + by);
            float2 o1 = make_float2(c[mt][nt][2] + bx, c[mt][nt][3] + by);
            *(float2*)&C[row * N + col] = o0;
            *(float2*)&C[(row + 8) * N + col] = o1;
        }
    }
}

// ---------------- 3) LSTM recurrence: k-split, batch-parallel ---------------
// 128 blocks x 8 rows; 1024 threads = kh(2 k-halves) x bg(4) x d(128).
// Each (kh,bg,d) thread: 2 rows, 4 gates over 64 k. kh=1 partials reduced
// into kh=0 through smem. h/c in fp32; global hs written tf32-rounded.
__global__ __launch_bounds__(1024) void lstm_kernel(const float* __restrict__ xW,
                                                    float* __restrict__ hs) {
    __shared__ float  h_s[8][128];
    __shared__ float4 pb[8][128];
    int t = threadIdx.x;
    int d = t & 127, bg = (t >> 7) & 3, kh = t >> 9;
    int r0 = bg * 2, r1 = r0 + 1;
    int b0 = blockIdx.x * 8;
    if (t < 1024) ((float*)h_s)[t] = 0.0f;
    float cc0 = 0.0f, cc1 = 0.0f;
    const int kbase = kh * 64;
    __syncthreads();
    for (int step = 0; step < Ss; step++) {
        float4 a0, a1;
        if (kh == 0) {
            int base0 = ((b0 + r0) * Ss + step) * G4;
            int base1 = ((b0 + r1) * Ss + step) * G4;
            a0 = make_float4(xW[base0 + d], xW[base0 + d + 128],
                             xW[base0 + d + 256], xW[base0 + d + 384]);
            a1 = make_float4(xW[base1 + d], xW[base1 + d + 128],
                             xW[base1 + d + 256], xW[base1 + d + 384]);
        } else {
            a0 = make_float4(0.f, 0.f, 0.f, 0.f);
            a1 = make_float4(0.f, 0.f, 0.f, 0.f);
        }
#pragma unroll 8
        for (int kk = 0; kk < 64; kk++) {
            int k = kbase + kk;
            float4 u = g_Ur[k * 128 + d];
            float h0 = h_s[r0][k], h1 = h_s[r1][k];
            a0.x += u.x * h0; a0.y += u.y * h0; a0.z += u.z * h0; a0.w += u.w * h0;
            a1.x += u.x * h1; a1.y += u.y * h1; a1.z += u.z * h1; a1.w += u.w * h1;
        }
        if (kh == 1) { pb[r0][d] = a0; pb[r1][d] = a1; }
        __syncthreads();
        if (kh == 0) {
            float4 p0 = pb[r0][d], p1 = pb[r1][d];
            a0.x += p0.x; a0.y += p0.y; a0.z += p0.z; a0.w += p0.w;
            a1.x += p1.x; a1.y += p1.y; a1.z += p1.z; a1.w += p1.w;
            float i0 = sigm(a0.x), f0 = sigm(a0.y), gg0 = tanhf(a0.z), o0 = sigm(a0.w);
            float i1 = sigm(a1.x), f1 = sigm(a1.y), gg1 = tanhf(a1.z), o1 = sigm(a1.w);
            cc0 = f0 * cc0 + i0 * gg0;  float hh0 = o0 * tanhf(cc0);
            cc1 = f1 * cc1 + i1 * gg1;  float hh1 = o1 * tanhf(cc1);
            h_s[r0][d] = hh0; h_s[r1][d] = hh1;
            hs[((b0 + r0) * Ss + step) * Dd + d] = to_tf32(hh0);
            hs[((b0 + r1) * Ss + step) * Dd + d] = to_tf32(hh1);
        }
        __syncthreads();
    }
}

// ---------------- 4) MHA core: one block per (b, head) ----------------------
__global__ __launch_bounds__(128) void mha_kernel() {
    int bh = blockIdx.x;
    int b = bh >> 2, h = bh & 3;
    __shared__ float qs[Ss][Ee], ks[Ss][Ee], vs[Ss][Ee];
    __shared__ float sc[Ss][52];
    int t = threadIdx.x;
    for (int idx = t; idx < Ss * Ee; idx += 128) {
        int s = idx >> 5, e = idx & 31;
        int base = (b * Ss + s) * 384 + h * Ee + e;
        qs[s][e] = g_qkv[base];
        ks[s][e] = g_qkv[base + 128];
        vs[s][e] = g_qkv[base + 256];
    }
    __syncthreads();
    const float scale = 0.17677669529663687f;  // 1/sqrt(32)
    for (int idx = t; idx < Ss * Ss; idx += 128) {
        int r = idx / Ss, c = idx % Ss;
        float a = 0.f;
#pragma unroll
        for (int e = 0; e < Ee; e++) a += qs[r][e] * ks[c][e];
        sc[r][c] = a * scale;
    }
    __syncthreads();
    if (t < Ss) {
        float mx = -3.4e38f;
        for (int c = 0; c < Ss; c++) mx = fmaxf(mx, sc[t][c]);
        float sm = 0.f;
        for (int c = 0; c < Ss; c++) { float e = __expf(sc[t][c] - mx); sc[t][c] = e; sm += e; }
        float inv = 1.f / sm;
        for (int c = 0; c < Ss; c++) sc[t][c] *= inv;
    }
    __syncthreads();
    for (int idx = t; idx < Ss * Ee; idx += 128) {
        int s = idx >> 5, e = idx & 31;
        float a = 0.f;
        for (int c = 0; c < Ss; c++) a += sc[s][c] * vs[c][e];
        g_att[(b * Ss + s) * Dd + h * Ee + e] = to_tf32(a);
    }
}

// ---------------- generic fp32 GEMM (kept for small W1) ---------------------
__global__ __launch_bounds__(256) void gemm64_kernel(
    const float* __restrict__ A, const float* __restrict__ W,
    const float* __restrict__ bias, float* __restrict__ C,
    int M, int N, int K) {
    __shared__ __align__(16) float As[16][68];
    __shared__ __align__(16) float Ws[16][68];
    int tid = threadIdx.x;
    int tx = tid & 15, ty = tid >> 4;
    int m0 = blockIdx.y * 64, n0 = blockIdx.x * 64;
    int ar = tid >> 2, ac4 = (tid & 3) * 4;
    int wr = tid >> 4, wc4 = (tid & 15) * 4;
    float acc[4][4] = {};
    for (int k0 = 0; k0 < K; k0 += 16) {
        float4 a4 = *(const float4*)&A[(m0 + ar) * K + k0 + ac4];
        float4 w4 = *(const float4*)&W[(k0 + wr) * N + n0 + wc4];
        __syncthreads();
        As[ac4 + 0][ar] = a4.x; As[ac4 + 1][ar] = a4.y;
        As[ac4 + 2][ar] = a4.z; As[ac4 + 3][ar] = a4.w;
        *(float4*)&Ws[wr][wc4] = w4;
        __syncthreads();
#pragma unroll
        for (int kk = 0; kk < 16; kk++) {
            float4 av = *(const float4*)&As[kk][ty * 4];
            float4 wv = *(const float4*)&Ws[kk][tx * 4];
            acc[0][0] += av.x * wv.x; acc[0][1] += av.x * wv.y; acc[0][2] += av.x * wv.z; acc[0][3] += av.x * wv.w;
            acc[1][0] += av.y * wv.x; acc[1][1] += av.y * wv.y; acc[1][2] += av.y * wv.z; acc[1][3] += av.y * wv.w;
            acc[2][0] += av.z * wv.x; acc[2][1] += av.z * wv.y; acc[2][2] += av.z * wv.z; acc[2][3] += av.z * wv.w;
            acc[3][0] += av.w * wv.x; acc[3][1] += av.w * wv.y; acc[3][2] += av.w * wv.z; acc[3][3] += av.w * wv.w;
        }
    }
    float b0x = 0.f, b0y = 0.f, b0z = 0.f, b0w = 0.f;
    if (bias) {
        const float* bp = bias + n0 + tx * 4;
        b0x = bp[0]; b0y = bp[1]; b0z = bp[2]; b0w = bp[3];
    }
#pragma unroll
    for (int i = 0; i < 4; i++) {
        float4 o = make_float4(acc[i][0] + b0x, acc[i][1] + b0y,
                               acc[i][2] + b0z, acc[i][3] + b0w);
        *(float4*)&C[(m0 + ty * 4 + i) * N + n0 + tx * 4] = o;
    }
}

// ---------------- 5) short-term attention pooling ---------------------------
__global__ __launch_bounds__(128) void shortpool_kernel() {
    int b = blockIdx.x;
    __shared__ float qv[Dd];
    __shared__ float sc[Ss];
    int t = threadIdx.x;
    qv[t] = g_qvec[b * Dd + t];
    __syncthreads();
    if (t < Ss) {
        const float* row = &g_stm[(b * Ss + t) * Dd];
        float a = 0.f;
        for (int k = 0; k < Dd; k++) a += row[k] * qv[k];
        sc[t] = a;
    }
    __syncthreads();
    if (t == 0) {
        float mx = -3.4e38f;
        for (int s = 0; s < Ss; s++) mx = fmaxf(mx, sc[s]);
        float sm = 0.f;
        for (int s = 0; s < Ss; s++) { float e = __expf(sc[s] - mx); sc[s] = e; sm += e; }
        float inv = 1.f / sm;
        for (int s = 0; s < Ss; s++) sc[s] *= inv;
    }
    __syncthreads();
    float a = 0.f;
    for (int s = 0; s < Ss; s++) a += sc[s] * g_stm[(b * Ss + s) * Dd + t];
    g_short[b * Dd + t] = a;
}

// ---------------- 6) long-term field attention (dedup mask) -----------------
__global__ __launch_bounds__(256) void longterm_kernel(const int* __restrict__ ltb,
                                                       const float* __restrict__ emb,
                                                       const float* __restrict__ Wt,
                                                       const float* __restrict__ bt) {
    int bi = blockIdx.x;
    int b = bi >> 2, fi = bi & 3;
    __shared__ int   ids[Ll];
    __shared__ float vecs[Ll][Ee];
    __shared__ float sc[Ll];
    __shared__ float uv[Ee];
    __shared__ float part[8][Ee];
    __shared__ float red[256];
    int t = threadIdx.x;
    if (t < Ll) ids[t] = ltb[(b * Ll + t) * Ff + fi];
    __syncthreads();
    for (int idx = t; idx < Ll * Ee; idx += 256) {
        int l = idx >> 5, e = idx & 31;
        vecs[l][e] = emb[ids[l] * Ee + e];
    }
    {
        int e = t & 31, g = t >> 5;
        float a = 0.f;
        for (int k = g * 32; k < g * 32 + 32; k++)
            a += g_user_e[b * UE + k] * Wt[(fi * UE + k) * Ee + e];
        part[g][e] = a;
    }
    __syncthreads();
    if (t < Ee) {
        float a = bt[fi * Ee + t];
        for (int g = 0; g < 8; g++) a += part[g][t];
        uv[t] = a;
    }
    __syncthreads();
    if (t < Ll) {
        int mid = ids[t];
        bool keep = true;
        for (int j = 0; j < t; j++) if (ids[j] == mid) { keep = false; break; }
        float a = 0.f;
#pragma unroll
        for (int e = 0; e < Ee; e++) a += vecs[t][e] * uv[e];
        sc[t] = keep ? a : NEGV;
    }
    __syncthreads();
    red[t] = (t < Ll) ? sc[t] : -3.4e38f;
    __syncthreads();
    for (int ofs = 128; ofs >= 1; ofs >>= 1) {
        if (t < ofs) red[t] = fmaxf(red[t], red[t + ofs]);
        __syncthreads();
    }
    float mx = red[0];
    __syncthreads();
    float ev = (t < Ll) ? __expf(sc[t] - mx) : 0.f;
    if (t < Ll) sc[t] = ev;
    red[t] = ev;
    __syncthreads();
    for (int ofs = 128; ofs >= 1; ofs >>= 1) {
        if (t < ofs) red[t] += red[t + ofs];
        __syncthreads();
    }
    float inv = 1.f / red[0];
    __syncthreads();
    {
        int e = t & 31, g = t >> 5;
        float a = 0.f;
        for (int l = g; l < Ll; l += 8) a += sc[l] * vecs[l][e];
        part[g][e] = a;
    }
    __syncthreads();
    if (t < Ee) {
        float a = 0.f;
        for (int g = 0; g < 8; g++) a += part[g][t];
        g_long[b * Dd + fi * Ee + t] = a * inv;
    }
}

// ---------------- 7) final gate + mix ---------------------------------------
__global__ __launch_bounds__(128) void gate_kernel(
    const float* __restrict__ Wu, const float* __restrict__ bu,
    const float* __restrict__ Wsg, const float* __restrict__ bsg,
    const float* __restrict__ Wl, const float* __restrict__ bl,
    float* __restrict__ out) {
    int b = blockIdx.x, d = threadIdx.x;
    __shared__ float ue[UE], sh[Dd], lg[Dd];
    ue[d] = g_user_e[b * UE + d];
    ue[d + 128] = g_user_e[b * UE + 128 + d];
    sh[d] = g_short[b * Dd + d];
    lg[d] = g_long[b * Dd + d];
    __syncthreads();
    float a = bu[d] + bsg[d] + bl[d];
    for (int k = 0; k < UE; k++) a += ue[k] * Wu[k * Dd + d];
    for (int k = 0; k < Dd; k++) a += sh[k] * Wsg[k * Dd + d] + lg[k] * Wl[k * Dd + d];
    float g = sigm(a);
    out[b * Dd + d] = (1.f - g) * lg[d] + g * sh[d];
}

// ---------------- host ------------------------------------------------------
static float* sym(const void* s) {
    void* p = nullptr;
    cudaGetSymbolAddress(&p, s);
    return (float*)p;
}

extern "C" void kernel_launch(void* const* d_in, const int* in_sizes, int n_in,
                              void* d_out, int out_size) {
    const int*   up     = (const int*)d_in[0];
    const int*   stb    = (const int*)d_in[1];
    const int*   ltb    = (const int*)d_in[2];
    const float* emb    = (const float*)d_in[3];
    const float* lstm_W = (const float*)d_in[4];
    const float* lstm_U = (const float*)d_in[5];
    const float* lstm_b = (const float*)d_in[6];
    const float* Wq     = (const float*)d_in[7];
    const float* Wk     = (const float*)d_in[8];
    const float* Wv     = (const float*)d_in[9];
    const float* Wo     = (const float*)d_in[10];
    const float* W1     = (const float*)d_in[11];
    const float* b1     = (const float*)d_in[12];
    const float* Wt     = (const float*)d_in[13];
    const float* bt     = (const float*)d_in[14];
    const float* Wu     = (const float*)d_in[15];
    const float* bu     = (const float*)d_in[16];
    const float* Wsg    = (const float*)d_in[17];
    const float* bsg    = (const float*)d_in[18];
    const float* Wl     = (const float*)d_in[19];
    const float* bl     = (const float*)d_in[20];
    float* out = (float*)d_out;

    float* p_user = sym(g_user_e);
    float* p_stx  = sym(g_stx);
    float* p_xW   = sym(g_xW);
    float* p_hs   = sym(g_hs);
    float* p_qkv  = sym(g_qkv);
    float* p_att  = sym(g_att);
    float* p_stm  = sym(g_stm);
    float* p_qvec = sym(g_qvec);
    float* p_Wr   = sym(g_Wr);
    float* p_Wqkv = sym(g_Wqkv);
    float* p_Wor  = sym(g_Wor);

    const int MBS = Bb * Ss;  // 51200

    // 1) gathers + weight repacks
    {
        int total = Bb * UE + Bb * Ss * Dd;
        gather_kernel<<<(total + 255) / 256, 256>>>(up, stb, emb);
        repackU_kernel<<<(Dd * Dd + 255) / 256, 256>>>(lstm_U);
        int wtotal = Dd * G4 + Dd * 384 + Dd * Dd;  // 131072
        repackW_kernel<<<(wtotal + 255) / 256, 256>>>(lstm_W, Wq, Wk, Wv, Wo);
    }
    // 2) xW = stx @ lstm_W + b   (51200 x 512 x 128) tf32
    gemm_tf32<<<dim3(G4 / 128, MBS / 128), 256>>>(p_stx, p_Wr, lstm_b, p_xW, MBS, G4, Dd);
    // 3) LSTM recurrence (fp32, k-split)
    lstm_kernel<<<Bb / 8, 1024>>>(p_xW, p_hs);
    // 4) fused QKV projection (51200 x 384 x 128) tf32
    gemm_tf32<<<dim3(384 / 128, MBS / 128), 256>>>(p_hs, p_Wqkv, nullptr, p_qkv, MBS, 384, Dd);
    // 5) attention core + output projection
    mha_kernel<<<Bb * Ff, 128>>>();
    gemm_tf32<<<dim3(Dd / 128, MBS / 128), 256>>>(p_att, p_Wor, nullptr, p_stm, MBS, Dd, Dd);
    // 6) pooling query (fp32, tiny) + short-term pooling
    gemm64_kernel<<<dim3(Dd / 64, Bb / 64), 256>>>(p_user, W1, b1, p_qvec, Bb, Dd, UE);
    shortpool_kernel<<<Bb, 128>>>();
    // 7) long-term field attention
    longterm_kernel<<<Bb * Ff, 256>>>(ltb, emb, Wt, bt);
    // 8) gate + mix -> out
    gate_kernel<<<Bb, 128>>>(Wu, bu, Wsg, bsg, Wl, bl, out);
}

// round 5
// speedup vs baseline: 2.0178x; 1.3849x over previous
#include <cuda_runtime.h>
#include <cuda_fp16.h>
#include <math.h>
#include <stdint.h>

// Problem constants
#define Bb   1024
#define Uu   8
#define Ss   50
#define Ll   200
#define Ff   4
#define Ee   32
#define Dd   128      // F*E
#define UE   256      // U*E
#define G4   512      // 4*D
#define NEGV -1000000000.0f

// ---------------- scratch (static device globals) ---------------------------
__device__ float  g_user_e[Bb * UE];          // (B,256)
__device__ float  g_user_t[Bb * UE];          // tf32-rounded copy
__device__ float  g_stx   [Bb * Ss * Dd];     // (B,50,128) tf32-rounded
__device__ float  g_xW    [Bb * Ss * G4];     // (B,50,512) x@W+b (fp32)
__device__ float  g_hs    [Bb * Ss * Dd];     // LSTM outputs (tf32-rounded)
__device__ float  g_qkv   [Bb * Ss * 384];    // fused q|k|v
__device__ float  g_att   [Bb * Ss * Dd];     // attn out, pre-Wo (tf32-rounded)
__device__ float  g_stm   [Bb * Ss * Dd];     // MHA out (post-Wo)
__device__ float  g_qvec  [Bb * Dd];
__device__ float  g_short [Bb * Dd];
__device__ float  g_long  [Bb * Dd];
__device__ __half g_Uh    [G4 * Dd];          // U^T as fp16: [n=512][k=128]
__device__ float  g_Wr    [Dd * G4];          // tf32-rounded lstm_W
__device__ float  g_Wqkv  [Dd * 384];         // tf32-rounded packed Wq|Wk|Wv
__device__ float  g_Wor   [Dd * Dd];          // tf32-rounded Wo
__device__ float  g_W1r   [UE * Dd];          // tf32-rounded W1

__device__ __forceinline__ float sigm(float x) { return 1.0f / (1.0f + __expf(-x)); }

__device__ __forceinline__ float to_tf32(float x) {
    uint32_t u;
    asm("cvt.rna.tf32.f32 %0, %1;" : "=r"(u) : "f"(x));
    return __uint_as_float(u);
}

__device__ __forceinline__ void cp16(void* smem, const void* g) {
    uint32_t s = (uint32_t)__cvta_generic_to_shared(smem);
    asm volatile("cp.async.ca.shared.global [%0], [%1], 16;" :: "r"(s), "l"(g));
}

__device__ __forceinline__ void mma_tf32(float* c, const uint32_t* a, const uint32_t* b) {
    asm volatile(
        "mma.sync.aligned.m16n8k8.row.col.f32.tf32.tf32.f32 "
        "{%0,%1,%2,%3}, {%4,%5,%6,%7}, {%8,%9}, {%0,%1,%2,%3};"
        : "+f"(c[0]), "+f"(c[1]), "+f"(c[2]), "+f"(c[3])
        : "r"(a[0]), "r"(a[1]), "r"(a[2]), "r"(a[3]), "r"(b[0]), "r"(b[1]));
}

__device__ __forceinline__ void mma_f16(float* c, const uint32_t* a, const uint32_t* b) {
    asm volatile(
        "mma.sync.aligned.m16n8k16.row.col.f32.f16.f16.f32 "
        "{%0,%1,%2,%3}, {%4,%5,%6,%7}, {%8,%9}, {%0,%1,%2,%3};"
        : "+f"(c[0]), "+f"(c[1]), "+f"(c[2]), "+f"(c[3])
        : "r"(a[0]), "r"(a[1]), "r"(a[2]), "r"(a[3]), "r"(b[0]), "r"(b[1]));
}

__device__ __forceinline__ void ldsm_x4(uint32_t& r0, uint32_t& r1, uint32_t& r2,
                                        uint32_t& r3, uint32_t addr) {
    asm volatile("ldmatrix.sync.aligned.m8n8.x4.shared.b16 {%0,%1,%2,%3}, [%4];"
                 : "=r"(r0), "=r"(r1), "=r"(r2), "=r"(r3) : "r"(addr));
}

__device__ __forceinline__ void ldsm_x2(uint32_t& r0, uint32_t& r1, uint32_t addr) {
    asm volatile("ldmatrix.sync.aligned.m8n8.x2.shared.b16 {%0,%1}, [%2];"
                 : "=r"(r0), "=r"(r1) : "r"(addr));
}

// ---------------- 1) embedding gathers --------------------------------------
__global__ void gather_kernel(const int* __restrict__ up, const int* __restrict__ stb,
                              const float* __restrict__ emb) {
    int idx = blockIdx.x * blockDim.x + threadIdx.x;
    const int n1 = Bb * UE;
    if (idx < n1) {
        int b = idx / UE, r = idx % UE;
        int u = r / Ee, e = r % Ee;
        float v = emb[up[b * Uu + u] * Ee + e];
        g_user_e[idx] = v;
        g_user_t[idx] = to_tf32(v);
    }
    int idx2 = idx - n1;
    if (idx2 >= 0 && idx2 < Bb * Ss * Dd) {
        int e = idx2 & (Ee - 1);
        int t = idx2 / Ee;            // (b*S+s)*F + f
        int f = t & (Ff - 1);
        int bs = t / Ff;              // b*S+s
        g_stx[idx2] = to_tf32(emb[stb[bs * Ff + f] * Ee + e]);
    }
}

// ---------------- 2) weight repacks ----------------------------------------
__global__ void repackU_kernel(const float* __restrict__ Uw) {
    int idx = blockIdx.x * blockDim.x + threadIdx.x;   // 65536
    if (idx >= G4 * Dd) return;
    int n = idx >> 7, k = idx & 127;
    g_Uh[idx] = __float2half(Uw[k * G4 + n]);
}

__global__ void repackW_kernel(const float* __restrict__ lstm_W,
                               const float* __restrict__ Wq,
                               const float* __restrict__ Wk,
                               const float* __restrict__ Wv,
                               const float* __restrict__ Wo,
                               const float* __restrict__ W1) {
    int idx = blockIdx.x * blockDim.x + threadIdx.x;
    if (idx < Dd * G4) {
        g_Wr[idx] = to_tf32(lstm_W[idx]);
        return;
    }
    int j = idx - Dd * G4;
    if (j < Dd * 384) {
        int k = j / 384, n = j % 384;
        float v = (n < 128) ? Wq[k * Dd + n]
                : (n < 256) ? Wk[k * Dd + (n - 128)]
                            : Wv[k * Dd + (n - 256)];
        g_Wqkv[j] = to_tf32(v);
        return;
    }
    j -= Dd * 384;
    if (j < Dd * Dd) { g_Wor[j] = to_tf32(Wo[j]); return; }
    j -= Dd * Dd;
    if (j < UE * Dd) g_W1r[j] = to_tf32(W1[j]);
}

// ---------------- tf32 tensor-core GEMM: C[M,N]=A[M,K]@W[K,N] (+bias) -------
__global__ __launch_bounds__(256, 2) void gemm_tf32(
    const float* __restrict__ A, const float* __restrict__ W,
    const float* __restrict__ bias, float* __restrict__ C,
    int M, int N, int K) {
    __shared__ float As[128][36];
    __shared__ float Bs[32][136];
    int tid = threadIdx.x;
    int lane = tid & 31, warp = tid >> 5;
    int wm = warp >> 1, wn = warp & 1;
    int g = lane >> 2, tig = lane & 3;
    int m0 = blockIdx.y * 128, n0 = blockIdx.x * 128;

    float c[2][8][4];
#pragma unroll
    for (int i = 0; i < 2; i++)
#pragma unroll
        for (int j = 0; j < 8; j++)
#pragma unroll
            for (int l = 0; l < 4; l++) c[i][j][l] = 0.f;

    for (int k0 = 0; k0 < K; k0 += 32) {
        if (k0) __syncthreads();
#pragma unroll
        for (int i = 0; i < 4; i++) {
            int idx = tid + i * 256;
            int r = idx >> 3, c4 = (idx & 7) * 4;
            cp16(&As[r][c4], &A[(m0 + r) * K + k0 + c4]);
        }
#pragma unroll
        for (int i = 0; i < 4; i++) {
            int idx = tid + i * 256;
            int r = idx >> 5, c4 = (idx & 31) * 4;
            cp16(&Bs[r][c4], &W[(k0 + r) * N + n0 + c4]);
        }
        asm volatile("cp.async.commit_group;");
        asm volatile("cp.async.wait_group 0;");
        __syncthreads();

#pragma unroll
        for (int kk = 0; kk < 32; kk += 8) {
            uint32_t a[2][4], b[8][2];
#pragma unroll
            for (int mt = 0; mt < 2; mt++) {
                int mr = wm * 32 + mt * 16;
                a[mt][0] = __float_as_uint(As[mr + g][kk + tig]);
                a[mt][1] = __float_as_uint(As[mr + g + 8][kk + tig]);
                a[mt][2] = __float_as_uint(As[mr + g][kk + tig + 4]);
                a[mt][3] = __float_as_uint(As[mr + g + 8][kk + tig + 4]);
            }
#pragma unroll
            for (int nt = 0; nt < 8; nt++) {
                int nc = wn * 64 + nt * 8 + g;
                b[nt][0] = __float_as_uint(Bs[kk + tig][nc]);
                b[nt][1] = __float_as_uint(Bs[kk + tig + 4][nc]);
            }
#pragma unroll
            for (int mt = 0; mt < 2; mt++)
#pragma unroll
                for (int nt = 0; nt < 8; nt++)
                    mma_tf32(c[mt][nt], a[mt], b[nt]);
        }
    }

#pragma unroll
    for (int mt = 0; mt < 2; mt++) {
        int row = m0 + wm * 32 + mt * 16 + g;
#pragma unroll
        for (int nt = 0; nt < 8; nt++) {
            int col = n0 + wn * 64 + nt * 8 + 2 * tig;
            float bx = 0.f, by = 0.f;
            if (bias) { bx = bias[col]; by = bias[col + 1]; }
            float2 o0 = make_float2(c[mt][nt][0] + bx, c[mt][nt][1] + by);
            float2 o1 = make_float2(c[mt][nt][2] + bx, c[mt][nt][3] + by);
            *(float2*)&C[row * N + col] = o0;
            *(float2*)&C[(row + 8) * N + col] = o1;
        }
    }
}

// ---------------- 3) LSTM: fp16 tensor-core recurrence, SMEM-resident U -----
#define UT_STRIDE 136          // fp16 elems per Ut row (conflict-free ldmatrix)
#define HB_STRIDE 136
#define ZB_STRIDE 520
#define LSTM_SMEM_BYTES (G4 * UT_STRIDE * 2 + 16 * HB_STRIDE * 2 + 8 * ZB_STRIDE * 4)

__global__ __launch_bounds__(256, 1) void lstm_mma_kernel(
    const float* __restrict__ xW, float* __restrict__ hs) {
    extern __shared__ __align__(16) char smem_raw[];
    __half* Ut   = (__half*)smem_raw;                              // [512][136]
    __half* hbuf = (__half*)(smem_raw + G4 * UT_STRIDE * 2);       // [16][136]
    float*  zbuf = (float*)(smem_raw + G4 * UT_STRIDE * 2 + 16 * HB_STRIDE * 2); // [8][520]

    int tid = threadIdx.x;
    int lane = tid & 31, warp = tid >> 5;
    int b0 = blockIdx.x * 8;

    // ---- load U^T into smem (cp.async), zero hbuf ----
    for (int i = tid; i < G4 * Dd / 8; i += 256) {     // 8192 16B chunks
        int n = i >> 4, c = (i & 15) * 8;
        cp16(&Ut[n * UT_STRIDE + c], &g_Uh[n * Dd + c]);
    }
    for (int i = tid; i < 16 * HB_STRIDE; i += 256) hbuf[i] = __float2half(0.f);
    asm volatile("cp.async.commit_group;");
    asm volatile("cp.async.wait_group 0;");
    __syncthreads();

    // ---- per-lane ldmatrix base addresses ----
    uint32_t hb_base = (uint32_t)__cvta_generic_to_shared(hbuf);
    uint32_t ut_base = (uint32_t)__cvta_generic_to_shared(Ut);
    int arow = lane & 15;
    int akofs = (lane >> 4) * 8;
    uint32_t aAddr = hb_base + (arow * HB_STRIDE + akofs) * 2;
    int bn = lane & 7;
    int bkofs = ((lane >> 3) & 1) * 8;
    int nw = warp * 64;
    uint32_t bAddr = ut_base + ((nw + bn) * UT_STRIDE + bkofs) * 2;

    int erow = tid >> 5, d0 = (tid & 31) * 4;
    float cc[4] = {0.f, 0.f, 0.f, 0.f};
    int gid = lane >> 2, tig = lane & 3;

    for (int step = 0; step < Ss; step++) {
        // prefetch xW gates (overlaps mma phase)
        const float* xb = xW + ((b0 + erow) * Ss + step) * G4 + d0;
        float4 xi = *(const float4*)&xb[0];
        float4 xf = *(const float4*)&xb[128];
        float4 xg = *(const float4*)&xb[256];
        float4 xo = *(const float4*)&xb[384];

        // ---- mma phase: acc[nt] = (h @ U)[rows, nw+nt*8 ..] ----
        float acc[8][4];
#pragma unroll
        for (int nt = 0; nt < 8; nt++)
#pragma unroll
            for (int j = 0; j < 4; j++) acc[nt][j] = 0.f;
#pragma unroll
        for (int kt = 0; kt < 8; kt++) {
            uint32_t a[4];
            ldsm_x4(a[0], a[1], a[2], a[3], aAddr + kt * 32);
#pragma unroll
            for (int nt = 0; nt < 8; nt++) {
                uint32_t b[2];
                ldsm_x2(b[0], b[1], bAddr + nt * (8 * UT_STRIDE * 2) + kt * 32);
                mma_f16(acc[nt], a, b);
            }
        }
        // dump z fragments (rows 0-7 live in c0/c1) to zbuf
#pragma unroll
        for (int nt = 0; nt < 8; nt++) {
            float2 v = make_float2(acc[nt][0], acc[nt][1]);
            *(float2*)&zbuf[gid * ZB_STRIDE + nw + nt * 8 + 2 * tig] = v;
        }
        __syncthreads();

        // ---- epilogue: gates, c/h update ----
        float4 zi = *(float4*)&zbuf[erow * ZB_STRIDE + d0];
        float4 zf = *(float4*)&zbuf[erow * ZB_STRIDE + 128 + d0];
        float4 zg = *(float4*)&zbuf[erow * ZB_STRIDE + 256 + d0];
        float4 zo = *(float4*)&zbuf[erow * ZB_STRIDE + 384 + d0];
        float hv[4];
        {
            float iv[4] = {zi.x + xi.x, zi.y + xi.y, zi.z + xi.z, zi.w + xi.w};
            float fv[4] = {zf.x + xf.x, zf.y + xf.y, zf.z + xf.z, zf.w + xf.w};
            float gv[4] = {zg.x + xg.x, zg.y + xg.y, zg.z + xg.z, zg.w + xg.w};
            float ov[4] = {zo.x + xo.x, zo.y + xo.y, zo.z + xo.z, zo.w + xo.w};
#pragma unroll
            for (int j = 0; j < 4; j++) {
                cc[j] = sigm(fv[j]) * cc[j] + sigm(iv[j]) * tanhf(gv[j]);
                hv[j] = sigm(ov[j]) * tanhf(cc[j]);
            }
        }
        __half2 h01 = __floats2half2_rn(hv[0], hv[1]);
        __half2 h23 = __floats2half2_rn(hv[2], hv[3]);
        *(__half2*)&hbuf[erow * HB_STRIDE + d0]     = h01;
        *(__half2*)&hbuf[erow * HB_STRIDE + d0 + 2] = h23;
        float4 ho = make_float4(to_tf32(hv[0]), to_tf32(hv[1]),
                                to_tf32(hv[2]), to_tf32(hv[3]));
        *(float4*)&hs[((b0 + erow) * Ss + step) * Dd + d0] = ho;
        __syncthreads();
    }
}

// ---------------- 4) MHA core: one block per (b, head) ----------------------
__global__ __launch_bounds__(128) void mha_kernel() {
    int bh = blockIdx.x;
    int b = bh >> 2, h = bh & 3;
    __shared__ float qs[Ss][Ee], ks[Ss][Ee], vs[Ss][Ee];
    __shared__ float sc[Ss][52];
    int t = threadIdx.x;
    for (int idx = t; idx < Ss * Ee; idx += 128) {
        int s = idx >> 5, e = idx & 31;
        int base = (b * Ss + s) * 384 + h * Ee + e;
        qs[s][e] = g_qkv[base];
        ks[s][e] = g_qkv[base + 128];
        vs[s][e] = g_qkv[base + 256];
    }
    __syncthreads();
    const float scale = 0.17677669529663687f;  // 1/sqrt(32)
    for (int idx = t; idx < Ss * Ss; idx += 128) {
        int r = idx / Ss, c = idx % Ss;
        float a = 0.f;
#pragma unroll
        for (int e = 0; e < Ee; e++) a += qs[r][e] * ks[c][e];
        sc[r][c] = a * scale;
    }
    __syncthreads();
    if (t < Ss) {
        float mx = -3.4e38f;
        for (int c = 0; c < Ss; c++) mx = fmaxf(mx, sc[t][c]);
        float sm = 0.f;
        for (int c = 0; c < Ss; c++) { float e = __expf(sc[t][c] - mx); sc[t][c] = e; sm += e; }
        float inv = 1.f / sm;
        for (int c = 0; c < Ss; c++) sc[t][c] *= inv;
    }
    __syncthreads();
    for (int idx = t; idx < Ss * Ee; idx += 128) {
        int s = idx >> 5, e = idx & 31;
        float a = 0.f;
        for (int c = 0; c < Ss; c++) a += sc[s][c] * vs[c][e];
        g_att[(b * Ss + s) * Dd + h * Ee + e] = to_tf32(a);
    }
}

// ---------------- 5) short-term attention pooling ---------------------------
__global__ __launch_bounds__(128) void shortpool_kernel() {
    int b = blockIdx.x;
    __shared__ float qv[Dd];
    __shared__ float sc[Ss];
    int t = threadIdx.x;
    qv[t] = g_qvec[b * Dd + t];
    __syncthreads();
    if (t < Ss) {
        const float* row = &g_stm[(b * Ss + t) * Dd];
        float a = 0.f;
        for (int k = 0; k < Dd; k++) a += row[k] * qv[k];
        sc[t] = a;
    }
    __syncthreads();
    if (t == 0) {
        float mx = -3.4e38f;
        for (int s = 0; s < Ss; s++) mx = fmaxf(mx, sc[s]);
        float sm = 0.f;
        for (int s = 0; s < Ss; s++) { float e = __expf(sc[s] - mx); sc[s] = e; sm += e; }
        float inv = 1.f / sm;
        for (int s = 0; s < Ss; s++) sc[s] *= inv;
    }
    __syncthreads();
    float a = 0.f;
    for (int s = 0; s < Ss; s++) a += sc[s] * g_stm[(b * Ss + s) * Dd + t];
    g_short[b * Dd + t] = a;
}

// ---------------- 6) long-term field attention (dedup mask) -----------------
__global__ __launch_bounds__(256) void longterm_kernel(const int* __restrict__ ltb,
                                                       const float* __restrict__ emb,
                                                       const float* __restrict__ Wt,
                                                       const float* __restrict__ bt) {
    int bi = blockIdx.x;
    int b = bi >> 2, fi = bi & 3;
    __shared__ int   ids[Ll];
    __shared__ float vecs[Ll][Ee];
    __shared__ float sc[Ll];
    __shared__ float uv[Ee];
    __shared__ float part[8][Ee];
    __shared__ float red[256];
    int t = threadIdx.x;
    if (t < Ll) ids[t] = ltb[(b * Ll + t) * Ff + fi];
    __syncthreads();
    for (int idx = t; idx < Ll * Ee; idx += 256) {
        int l = idx >> 5, e = idx & 31;
        vecs[l][e] = emb[ids[l] * Ee + e];
    }
    {
        int e = t & 31, g = t >> 5;
        float a = 0.f;
        for (int k = g * 32; k < g * 32 + 32; k++)
            a += g_user_e[b * UE + k] * Wt[(fi * UE + k) * Ee + e];
        part[g][e] = a;
    }
    __syncthreads();
    if (t < Ee) {
        float a = bt[fi * Ee + t];
        for (int g = 0; g < 8; g++) a += part[g][t];
        uv[t] = a;
    }
    __syncthreads();
    if (t < Ll) {
        int mid = ids[t];
        bool keep = true;
        for (int j = 0; j < t; j++) if (ids[j] == mid) { keep = false; break; }
        float a = 0.f;
#pragma unroll
        for (int e = 0; e < Ee; e++) a += vecs[t][e] * uv[e];
        sc[t] = keep ? a : NEGV;
    }
    __syncthreads();
    red[t] = (t < Ll) ? sc[t] : -3.4e38f;
    __syncthreads();
    for (int ofs = 128; ofs >= 1; ofs >>= 1) {
        if (t < ofs) red[t] = fmaxf(red[t], red[t + ofs]);
        __syncthreads();
    }
    float mx = red[0];
    __syncthreads();
    float ev = (t < Ll) ? __expf(sc[t] - mx) : 0.f;
    if (t < Ll) sc[t] = ev;
    red[t] = ev;
    __syncthreads();
    for (int ofs = 128; ofs >= 1; ofs >>= 1) {
        if (t < ofs) red[t] += red[t + ofs];
        __syncthreads();
    }
    float inv = 1.f / red[0];
    __syncthreads();
    {
        int e = t & 31, g = t >> 5;
        float a = 0.f;
        for (int l = g; l < Ll; l += 8) a += sc[l] * vecs[l][e];
        part[g][e] = a;
    }
    __syncthreads();
    if (t < Ee) {
        float a = 0.f;
        for (int g = 0; g < 8; g++) a += part[g][t];
        g_long[b * Dd + fi * Ee + t] = a * inv;
    }
}

// ---------------- 7) final gate + mix ---------------------------------------
__global__ __launch_bounds__(128) void gate_kernel(
    const float* __restrict__ Wu, const float* __restrict__ bu,
    const float* __restrict__ Wsg, const float* __restrict__ bsg,
    const float* __restrict__ Wl, const float* __restrict__ bl,
    float* __restrict__ out) {
    int b = blockIdx.x, d = threadIdx.x;
    __shared__ float ue[UE], sh[Dd], lg[Dd];
    ue[d] = g_user_e[b * UE + d];
    ue[d + 128] = g_user_e[b * UE + 128 + d];
    sh[d] = g_short[b * Dd + d];
    lg[d] = g_long[b * Dd + d];
    __syncthreads();
    float a = bu[d] + bsg[d] + bl[d];
    for (int k = 0; k < UE; k++) a += ue[k] * Wu[k * Dd + d];
    for (int k = 0; k < Dd; k++) a += sh[k] * Wsg[k * Dd + d] + lg[k] * Wl[k * Dd + d];
    float g = sigm(a);
    out[b * Dd + d] = (1.f - g) * lg[d] + g * sh[d];
}

// ---------------- host ------------------------------------------------------
static float* sym(const void* s) {
    void* p = nullptr;
    cudaGetSymbolAddress(&p, s);
    return (float*)p;
}

extern "C" void kernel_launch(void* const* d_in, const int* in_sizes, int n_in,
                              void* d_out, int out_size) {
    const int*   up     = (const int*)d_in[0];
    const int*   stb    = (const int*)d_in[1];
    const int*   ltb    = (const int*)d_in[2];
    const float* emb    = (const float*)d_in[3];
    const float* lstm_W = (const float*)d_in[4];
    const float* lstm_U = (const float*)d_in[5];
    const float* lstm_b = (const float*)d_in[6];
    const float* Wq     = (const float*)d_in[7];
    const float* Wk     = (const float*)d_in[8];
    const float* Wv     = (const float*)d_in[9];
    const float* Wo     = (const float*)d_in[10];
    const float* W1     = (const float*)d_in[11];
    const float* b1     = (const float*)d_in[12];
    const float* Wt     = (const float*)d_in[13];
    const float* bt     = (const float*)d_in[14];
    const float* Wu     = (const float*)d_in[15];
    const float* bu     = (const float*)d_in[16];
    const float* Wsg    = (const float*)d_in[17];
    const float* bsg    = (const float*)d_in[18];
    const float* Wl     = (const float*)d_in[19];
    const float* bl     = (const float*)d_in[20];
    float* out = (float*)d_out;

    float* p_user  = sym(g_user_e);
    float* p_usert = sym(g_user_t);
    float* p_stx   = sym(g_stx);
    float* p_xW    = sym(g_xW);
    float* p_hs    = sym(g_hs);
    float* p_qkv   = sym(g_qkv);
    float* p_att   = sym(g_att);
    float* p_stm   = sym(g_stm);
    float* p_qvec  = sym(g_qvec);
    float* p_Wr    = sym(g_Wr);
    float* p_Wqkv  = sym(g_Wqkv);
    float* p_Wor   = sym(g_Wor);
    float* p_W1r   = sym(g_W1r);

    const int MBS = Bb * Ss;  // 51200

    // no static guards: idempotent, every call
    cudaFuncSetAttribute(lstm_mma_kernel,
                         cudaFuncAttributeMaxDynamicSharedMemorySize,
                         LSTM_SMEM_BYTES);

    // 1) gathers + weight repacks
    {
        int total = Bb * UE + Bb * Ss * Dd;
        gather_kernel<<<(total + 255) / 256, 256>>>(up, stb, emb);
        repackU_kernel<<<(G4 * Dd + 255) / 256, 256>>>(lstm_U);
        int wtotal = Dd * G4 + Dd * 384 + Dd * Dd + UE * Dd;
        repackW_kernel<<<(wtotal + 255) / 256, 256>>>(lstm_W, Wq, Wk, Wv, Wo, W1);
    }
    // 2) xW = stx @ lstm_W + b   (51200 x 512 x 128) tf32
    gemm_tf32<<<dim3(G4 / 128, MBS / 128), 256>>>(p_stx, p_Wr, lstm_b, p_xW, MBS, G4, Dd);
    // 3) LSTM recurrence: fp16 mma, SMEM-resident U, 128 CTAs x 8 rows
    lstm_mma_kernel<<<Bb / 8, 256, LSTM_SMEM_BYTES>>>(p_xW, p_hs);
    // 4) fused QKV projection (51200 x 384 x 128) tf32
    gemm_tf32<<<dim3(384 / 128, MBS / 128), 256>>>(p_hs, p_Wqkv, nullptr, p_qkv, MBS, 384, Dd);
    // 5) attention core + output projection
    mha_kernel<<<Bb * Ff, 128>>>();
    gemm_tf32<<<dim3(Dd / 128, MBS / 128), 256>>>(p_att, p_Wor, nullptr, p_stm, MBS, Dd, Dd);
    // 6) pooling query (tf32) + short-term pooling
    gemm_tf32<<<dim3(Dd / 128, Bb / 128), 256>>>(p_usert, p_W1r, b1, p_qvec, Bb, Dd, UE);
    shortpool_kernel<<<Bb, 128>>>();
    // 7) long-term field attention
    longterm_kernel<<<Bb * Ff, 256>>>(ltb, emb, Wt, bt);
    // 8) gate + mix -> out
    gate_kernel<<<Bb, 128>>>(Wu, bu, Wsg, bsg, Wl, bl, out);
}